// round 1
// baseline (speedup 1.0000x reference)
#include <cuda_runtime.h>

#define T_ 512
#define B_ 4
#define H_ 16
#define D_ 64
#define NBKT 32
#define TOKENS 1536           // (1+NGRAM)*T
#define ROWS_ (TOKENS * B_)   // 6144

// Scratch (device globals: allocation-free rule)
__device__ float g_qkv[ROWS_ * 3072];  // q|k|v per row, q pre-scaled by 1/8
__device__ float g_rel[ROWS_ * 512];   // rel-value table, col = bucket*16 + head
__device__ float g_ctx[ROWS_ * 1024];  // attention output pre out-proj

// ---------------------------------------------------------------------------
// SGEMM: C[M,N] = A[M,K] @ B[N,K]^T + bias, cols < scale_cols scaled by `scale`
// BM=BN=128, BK=8, 256 threads, 8x8 microtile. All dims multiples of 128/8.
// ---------------------------------------------------------------------------
__global__ __launch_bounds__(256) void sgemm_nt(
    const float* __restrict__ A, const float* __restrict__ Bm,
    const float* __restrict__ bias, float* __restrict__ C,
    int M, int N, int K, int scale_cols, float scale)
{
    __shared__ float As[8][128];
    __shared__ float Bs[8][128];
    const int tid  = threadIdx.x;
    const int row0 = blockIdx.y * 128;
    const int col0 = blockIdx.x * 128;
    const int lr = tid >> 1;          // 0..127
    const int lk = (tid & 1) << 2;    // 0 or 4
    const int ty = tid >> 4, tx = tid & 15;

    const float* Ap = A  + (size_t)(row0 + lr) * K + lk;
    const float* Bp = Bm + (size_t)(col0 + lr) * K + lk;

    float acc[8][8];
    #pragma unroll
    for (int i = 0; i < 8; i++)
        #pragma unroll
        for (int j = 0; j < 8; j++) acc[i][j] = 0.f;

    for (int k0 = 0; k0 < K; k0 += 8) {
        float4 av = *(const float4*)(Ap + k0);
        float4 bv = *(const float4*)(Bp + k0);
        As[lk+0][lr] = av.x; As[lk+1][lr] = av.y; As[lk+2][lr] = av.z; As[lk+3][lr] = av.w;
        Bs[lk+0][lr] = bv.x; Bs[lk+1][lr] = bv.y; Bs[lk+2][lr] = bv.z; Bs[lk+3][lr] = bv.w;
        __syncthreads();
        #pragma unroll
        for (int kk = 0; kk < 8; kk++) {
            float4 a0 = *(const float4*)&As[kk][ty*8];
            float4 a1 = *(const float4*)&As[kk][ty*8 + 4];
            float4 b0 = *(const float4*)&Bs[kk][tx*8];
            float4 b1 = *(const float4*)&Bs[kk][tx*8 + 4];
            float a[8] = {a0.x,a0.y,a0.z,a0.w,a1.x,a1.y,a1.z,a1.w};
            float b[8] = {b0.x,b0.y,b0.z,b0.w,b1.x,b1.y,b1.z,b1.w};
            #pragma unroll
            for (int i = 0; i < 8; i++)
                #pragma unroll
                for (int j = 0; j < 8; j++)
                    acc[i][j] = fmaf(a[i], b[j], acc[i][j]);
        }
        __syncthreads();
    }

    #pragma unroll
    for (int i = 0; i < 8; i++) {
        int r = row0 + ty*8 + i;
        #pragma unroll
        for (int j = 0; j < 8; j++) {
            int c = col0 + tx*8 + j;
            float v = acc[i][j] + (bias ? bias[c] : 0.f);
            if (c < scale_cols) v *= scale;
            C[(size_t)r * N + c] = v;
        }
    }
}

// ---------------------------------------------------------------------------
// Fused flash attention (main + ngram), BM=32 q rows x BN=64 keys, d=64.
// Scores = q.k + rel[bucket(t,s)] + mask(t,s); online softmax; PV accum.
// grid: (T/BM, B*H, 1 or NGRAM). 256 threads.
// ---------------------------------------------------------------------------
#define BM 32
#define BN 64

__global__ __launch_bounds__(256) void attn_kernel(
    const float* __restrict__ qkv, const float* __restrict__ rel,
    const float* __restrict__ mask, const int* __restrict__ buckets,
    float* __restrict__ ctx, int is_ngram)
{
    const int bh = blockIdx.y;
    const int b  = bh >> 4;
    const int h  = bh & 15;
    const int n  = blockIdx.z;
    const int t0 = blockIdx.x * BM;
    const int S  = is_ngram ? 2*T_ : T_;
    const int qtok0 = is_ngram ? (T_ + n*T_ + t0) : t0;

    __shared__ float sQt[D_][BM + 4];        // [k][m]
    __shared__ float sKV[D_ * (BN + 4)];     // K as [k][s] pitch 68, V as [s][d] pitch 68
    __shared__ float sP[BM][BN + 4];
    __shared__ float sRel[BM][NBKT];
    __shared__ float sM[BM], sL[BM], sScale[BM];

    const int tid = threadIdx.x;
    const int tx  = tid & 15, ty = tid >> 4;

    // Q tile (transposed) : 32 rows x 64 cols, q cols are [0,1024) of qkv (pre-scaled)
    #pragma unroll
    for (int p = 0; p < 2; p++) {
        int idx = tid + p*256;
        int r  = idx >> 4;
        int c4 = (idx & 15) << 2;
        float4 v = *(const float4*)(qkv + (size_t)((qtok0 + r)*B_ + b)*3072 + h*D_ + c4);
        sQt[c4+0][r] = v.x; sQt[c4+1][r] = v.y; sQt[c4+2][r] = v.z; sQt[c4+3][r] = v.w;
    }
    // rel LUT: per local row, 32 bucket values for this head
    #pragma unroll
    for (int p = 0; p < 4; p++) {
        int idx = tid + p*256;
        int r  = idx >> 5;
        int bk = idx & 31;
        sRel[r][bk] = rel[(size_t)((qtok0 + r)*B_ + b)*512 + bk*H_ + h];
    }
    if (tid < BM) { sM[tid] = -1e30f; sL[tid] = 0.f; }

    float accO[2][4];
    #pragma unroll
    for (int i = 0; i < 2; i++)
        #pragma unroll
        for (int j = 0; j < 4; j++) accO[i][j] = 0.f;

    const float* maskrow = is_ngram ? (mask + (size_t)n * T_ * 1024) : mask;
    const int*   brow    = is_ngram ? (buckets + (size_t)b * T_ * 1024)
                                    : (buckets + (size_t)b * T_ * 512);

    for (int s0 = 0; s0 < S; s0 += BN) {
        __syncthreads();  // (a) prior PV done with sKV/sP; first iter: Q/rel ready
        // K tile transposed [k][s]
        #pragma unroll
        for (int p = 0; p < 4; p++) {
            int idx = tid + p*256;
            int sr = idx >> 4;
            int c4 = (idx & 15) << 2;
            int sg = s0 + sr;
            int tok = (!is_ngram || sg < T_) ? sg : (T_ + n*T_ + (sg - T_));
            float4 v = *(const float4*)(qkv + (size_t)(tok*B_ + b)*3072 + 1024 + h*D_ + c4);
            sKV[(c4+0)*(BN+4) + sr] = v.x;
            sKV[(c4+1)*(BN+4) + sr] = v.y;
            sKV[(c4+2)*(BN+4) + sr] = v.z;
            sKV[(c4+3)*(BN+4) + sr] = v.w;
        }
        __syncthreads();  // (b) K ready

        // scores 2x4 microtile
        float sc[2][4] = {{0.f,0.f,0.f,0.f},{0.f,0.f,0.f,0.f}};
        #pragma unroll
        for (int kk = 0; kk < D_; kk++) {
            float2 aa = *(const float2*)&sQt[kk][ty*2];
            float4 bb = *(const float4*)&sKV[kk*(BN+4) + tx*4];
            sc[0][0] = fmaf(aa.x, bb.x, sc[0][0]);
            sc[0][1] = fmaf(aa.x, bb.y, sc[0][1]);
            sc[0][2] = fmaf(aa.x, bb.z, sc[0][2]);
            sc[0][3] = fmaf(aa.x, bb.w, sc[0][3]);
            sc[1][0] = fmaf(aa.y, bb.x, sc[1][0]);
            sc[1][1] = fmaf(aa.y, bb.y, sc[1][1]);
            sc[1][2] = fmaf(aa.y, bb.z, sc[1][2]);
            sc[1][3] = fmaf(aa.y, bb.w, sc[1][3]);
        }
        // + rel + mask -> sP
        #pragma unroll
        for (int i = 0; i < 2; i++) {
            int r  = ty*2 + i;
            int tg = t0 + r;
            #pragma unroll
            for (int j = 0; j < 4; j++) {
                int sg  = s0 + tx*4 + j;
                int bkt = brow[(size_t)tg * S + sg];
                sP[r][tx*4+j] = sc[i][j] + sRel[r][bkt] + maskrow[(size_t)tg * S + sg];
            }
        }
        __syncthreads();  // (c) sP ready, K reads done -> sKV reusable

        // V tile [s][d] into sKV (all threads)
        #pragma unroll
        for (int p = 0; p < 4; p++) {
            int idx = tid + p*256;
            int sr = idx >> 4;
            int c4 = (idx & 15) << 2;
            int sg = s0 + sr;
            int tok = (!is_ngram || sg < T_) ? sg : (T_ + n*T_ + (sg - T_));
            float4 v = *(const float4*)(qkv + (size_t)(tok*B_ + b)*3072 + 2048 + h*D_ + c4);
            *(float4*)&sKV[sr*(D_+4) + c4] = v;
        }

        // online softmax: 8 threads per row
        {
            int r = tid >> 3;
            int g = tid & 7;
            float mx = -1e30f;
            #pragma unroll
            for (int q = 0; q < 8; q++) mx = fmaxf(mx, sP[r][g + q*8]);
            mx = fmaxf(mx, __shfl_xor_sync(0xffffffffu, mx, 1));
            mx = fmaxf(mx, __shfl_xor_sync(0xffffffffu, mx, 2));
            mx = fmaxf(mx, __shfl_xor_sync(0xffffffffu, mx, 4));
            float oldm = sM[r];
            float newm = fmaxf(oldm, mx);
            float sum = 0.f;
            #pragma unroll
            for (int q = 0; q < 8; q++) {
                float pv = __expf(sP[r][g + q*8] - newm);
                sP[r][g + q*8] = pv;
                sum += pv;
            }
            sum += __shfl_xor_sync(0xffffffffu, sum, 1);
            sum += __shfl_xor_sync(0xffffffffu, sum, 2);
            sum += __shfl_xor_sync(0xffffffffu, sum, 4);
            if (g == 0) {
                float sc_ = __expf(oldm - newm);
                sScale[r] = sc_;
                sL[r] = sL[r]*sc_ + sum;
                sM[r] = newm;
            }
        }
        __syncthreads();  // (d) V + exp(P) + sScale ready

        // rescale + PV
        #pragma unroll
        for (int i = 0; i < 2; i++) {
            float f = sScale[ty*2 + i];
            #pragma unroll
            for (int j = 0; j < 4; j++) accO[i][j] *= f;
        }
        #pragma unroll 8
        for (int s = 0; s < BN; s++) {
            float p0 = sP[ty*2][s];
            float p1 = sP[ty*2 + 1][s];
            float4 v = *(const float4*)&sKV[s*(D_+4) + tx*4];
            accO[0][0] = fmaf(p0, v.x, accO[0][0]);
            accO[0][1] = fmaf(p0, v.y, accO[0][1]);
            accO[0][2] = fmaf(p0, v.z, accO[0][2]);
            accO[0][3] = fmaf(p0, v.w, accO[0][3]);
            accO[1][0] = fmaf(p1, v.x, accO[1][0]);
            accO[1][1] = fmaf(p1, v.y, accO[1][1]);
            accO[1][2] = fmaf(p1, v.z, accO[1][2]);
            accO[1][3] = fmaf(p1, v.w, accO[1][3]);
        }
    }

    #pragma unroll
    for (int i = 0; i < 2; i++) {
        int r = ty*2 + i;
        float inv = 1.f / sL[r];
        float4 o = make_float4(accO[i][0]*inv, accO[i][1]*inv, accO[i][2]*inv, accO[i][3]*inv);
        *(float4*)(ctx + (size_t)((qtok0 + r)*B_ + b)*1024 + h*D_ + tx*4) = o;
    }
}

// ---------------------------------------------------------------------------
extern "C" void kernel_launch(void* const* d_in, const int* in_sizes, int n_in,
                              void* d_out, int out_size)
{
    const float* hs        = (const float*)d_in[0];   // (1536,4,1024)
    const float* w_in      = (const float*)d_in[1];   // (3072,1024)
    const float* b_in      = (const float*)d_in[2];   // (3072,)
    const float* rw        = (const float*)d_in[3];   // (512,1024)
    const float* rb        = (const float*)d_in[4];   // (512,)
    const float* ow        = (const float*)d_in[5];   // (1024,1024)
    const float* ob        = (const float*)d_in[6];   // (1024,)
    const float* mask_main = (const float*)d_in[7];   // (512,512)
    const float* mask_ng   = (const float*)d_in[8];   // (2,512,1024)
    const int*   ib_main   = (const int*)d_in[9];     // (4,512,512)
    const int*   ib_ng     = (const int*)d_in[10];    // (4,512,1024)
    float* out = (float*)d_out;

    float *qkv, *rel, *ctx;
    cudaGetSymbolAddress((void**)&qkv, g_qkv);
    cudaGetSymbolAddress((void**)&rel, g_rel);
    cudaGetSymbolAddress((void**)&ctx, g_ctx);

    // QKV projection; q columns [0,1024) pre-scaled by d^-0.5 = 0.125
    sgemm_nt<<<dim3(3072/128, ROWS_/128), 256>>>(hs, w_in, b_in, qkv,
                                                 ROWS_, 3072, 1024, 1024, 0.125f);
    // rel-value table
    sgemm_nt<<<dim3(512/128, ROWS_/128), 256>>>(hs, rw, rb, rel,
                                                ROWS_, 512, 1024, 0, 1.f);
    // fused attention
    attn_kernel<<<dim3(T_/BM, B_*H_, 1), 256>>>(qkv, rel, mask_main, ib_main, ctx, 0);
    attn_kernel<<<dim3(T_/BM, B_*H_, 2), 256>>>(qkv, rel, mask_ng,   ib_ng,   ctx, 1);
    // out projection directly into d_out
    sgemm_nt<<<dim3(1024/128, ROWS_/128), 256>>>(ctx, ow, ob, out,
                                                 ROWS_, 1024, 1024, 0, 1.f);
}

// round 2
// speedup vs baseline: 1.2682x; 1.2682x over previous
#include <cuda_runtime.h>

#define T_ 512
#define B_ 4
#define H_ 16
#define D_ 64
#define NBKT 32
#define TOKENS 1536           // (1+NGRAM)*T
#define ROWS_ (TOKENS * B_)   // 6144

typedef unsigned long long ull;

// Scratch (device globals: allocation-free rule)
__device__ float g_qkv[ROWS_ * 3072];  // q|k|v per row, q pre-scaled by 1/8
__device__ float g_rel[ROWS_ * 512];   // rel-value table, col = bucket*16 + head
__device__ float g_ctx[ROWS_ * 1024];  // attention output pre out-proj

// ---- packed f32x2 helpers (SASS FFMA2 path; ptxas won't auto-fuse) ----
__device__ __forceinline__ ull dup2(float x) {
    ull r; asm("mov.b64 %0, {%1, %2};" : "=l"(r) : "f"(x), "f"(x)); return r;
}
__device__ __forceinline__ float2 unpack2(ull v) {
    float2 f; asm("mov.b64 {%0, %1}, %2;" : "=f"(f.x), "=f"(f.y) : "l"(v)); return f;
}
__device__ __forceinline__ void fma2(ull& d, ull a, ull b) {
    asm("fma.rn.f32x2 %0, %1, %2, %0;" : "+l"(d) : "l"(a), "l"(b));
}
__device__ __forceinline__ ull mul2(ull a, ull b) {
    ull r; asm("mul.rn.f32x2 %0, %1, %2;" : "=l"(r) : "l"(a), "l"(b)); return r;
}

// ---------------------------------------------------------------------------
// SGEMM: C[M,N] = A[M,K] @ B[N,K]^T + bias, cols < scale_cols scaled by `scale`
// BM=BN=128, BK=8, 256 threads, 8x8 microtile, f32x2 accumulators.
// ---------------------------------------------------------------------------
__global__ __launch_bounds__(256) void sgemm_nt(
    const float* __restrict__ A, const float* __restrict__ Bm,
    const float* __restrict__ bias, float* __restrict__ C,
    int M, int N, int K, int scale_cols, float scale)
{
    __shared__ float As[8][128];
    __shared__ float Bs[8][128];
    const int tid  = threadIdx.x;
    const int row0 = blockIdx.y * 128;
    const int col0 = blockIdx.x * 128;
    const int lr = tid >> 1;          // 0..127
    const int lk = (tid & 1) << 2;    // 0 or 4
    const int ty = tid >> 4, tx = tid & 15;

    const float* Ap = A  + (size_t)(row0 + lr) * K + lk;
    const float* Bp = Bm + (size_t)(col0 + lr) * K + lk;

    ull acc[8][4];
    #pragma unroll
    for (int i = 0; i < 8; i++)
        #pragma unroll
        for (int j = 0; j < 4; j++) acc[i][j] = 0ull;

    float4 av = *(const float4*)(Ap);
    float4 bv = *(const float4*)(Bp);

    for (int k0 = 0; k0 < K; k0 += 8) {
        As[lk+0][lr] = av.x; As[lk+1][lr] = av.y; As[lk+2][lr] = av.z; As[lk+3][lr] = av.w;
        Bs[lk+0][lr] = bv.x; Bs[lk+1][lr] = bv.y; Bs[lk+2][lr] = bv.z; Bs[lk+3][lr] = bv.w;
        __syncthreads();
        if (k0 + 8 < K) {
            av = *(const float4*)(Ap + k0 + 8);
            bv = *(const float4*)(Bp + k0 + 8);
        }
        #pragma unroll
        for (int kk = 0; kk < 8; kk++) {
            float4 a0 = *(const float4*)&As[kk][ty*8];
            float4 a1 = *(const float4*)&As[kk][ty*8 + 4];
            ull b0 = *(const ull*)&Bs[kk][tx*8];
            ull b1 = *(const ull*)&Bs[kk][tx*8 + 2];
            ull b2 = *(const ull*)&Bs[kk][tx*8 + 4];
            ull b3 = *(const ull*)&Bs[kk][tx*8 + 6];
            ull d;
            d = dup2(a0.x); fma2(acc[0][0],d,b0); fma2(acc[0][1],d,b1); fma2(acc[0][2],d,b2); fma2(acc[0][3],d,b3);
            d = dup2(a0.y); fma2(acc[1][0],d,b0); fma2(acc[1][1],d,b1); fma2(acc[1][2],d,b2); fma2(acc[1][3],d,b3);
            d = dup2(a0.z); fma2(acc[2][0],d,b0); fma2(acc[2][1],d,b1); fma2(acc[2][2],d,b2); fma2(acc[2][3],d,b3);
            d = dup2(a0.w); fma2(acc[3][0],d,b0); fma2(acc[3][1],d,b1); fma2(acc[3][2],d,b2); fma2(acc[3][3],d,b3);
            d = dup2(a1.x); fma2(acc[4][0],d,b0); fma2(acc[4][1],d,b1); fma2(acc[4][2],d,b2); fma2(acc[4][3],d,b3);
            d = dup2(a1.y); fma2(acc[5][0],d,b0); fma2(acc[5][1],d,b1); fma2(acc[5][2],d,b2); fma2(acc[5][3],d,b3);
            d = dup2(a1.z); fma2(acc[6][0],d,b0); fma2(acc[6][1],d,b1); fma2(acc[6][2],d,b2); fma2(acc[6][3],d,b3);
            d = dup2(a1.w); fma2(acc[7][0],d,b0); fma2(acc[7][1],d,b1); fma2(acc[7][2],d,b2); fma2(acc[7][3],d,b3);
        }
        __syncthreads();
    }

    float4 bia0 = make_float4(0.f,0.f,0.f,0.f), bia1 = bia0;
    if (bias) {
        bia0 = *(const float4*)&bias[col0 + tx*8];
        bia1 = *(const float4*)&bias[col0 + tx*8 + 4];
    }
    #pragma unroll
    for (int i = 0; i < 8; i++) {
        int r = row0 + ty*8 + i;
        float2 p0 = unpack2(acc[i][0]);
        float2 p1 = unpack2(acc[i][1]);
        float2 p2 = unpack2(acc[i][2]);
        float2 p3 = unpack2(acc[i][3]);
        float o[8] = { p0.x + bia0.x, p0.y + bia0.y, p1.x + bia0.z, p1.y + bia0.w,
                       p2.x + bia1.x, p2.y + bia1.y, p3.x + bia1.z, p3.y + bia1.w };
        #pragma unroll
        for (int j = 0; j < 8; j++) {
            int c = col0 + tx*8 + j;
            if (c < scale_cols) o[j] *= scale;
        }
        *(float4*)&C[(size_t)r * N + col0 + tx*8]     = make_float4(o[0],o[1],o[2],o[3]);
        *(float4*)&C[(size_t)r * N + col0 + tx*8 + 4] = make_float4(o[4],o[5],o[6],o[7]);
    }
}

// ---------------------------------------------------------------------------
// Fused flash attention (main + ngram in one launch), BM=64 x BN=64, d=64.
// 256 threads, 4x4 microtiles with f32x2 accumulators.
// grid: (T/64, B*H, 3) — z=0: main (S=512), z=1,2: ngram n=z-1 (S=1024).
// ---------------------------------------------------------------------------
#define BM2 64
#define BN2 64
#define DP  68

__global__ __launch_bounds__(256) void attn_kernel(
    const float* __restrict__ qkv, const float* __restrict__ rel,
    const float* __restrict__ mask_main, const float* __restrict__ mask_ng,
    const int* __restrict__ ib_main, const int* __restrict__ ib_ng,
    float* __restrict__ ctx)
{
    extern __shared__ float smem[];
    float* sQt   = smem;               // [64][DP]  Q^T (k-major)
    float* sK    = sQt + 64*DP;        // [64][DP]  K^T, later V[s][d]
    float* sP    = sK  + 64*DP;        // [64][DP]
    float* sRel  = sP  + 64*DP;        // [64][32]
    float* sM    = sRel + 64*32;
    float* sL    = sM + 64;
    float* sScale= sL + 64;

    const int bh = blockIdx.y;
    const int b  = bh >> 4;
    const int h  = bh & 15;
    const int z  = blockIdx.z;
    const int is_ng = (z > 0);
    const int n  = z - 1;
    const int t0 = blockIdx.x * BM2;
    const int S  = is_ng ? 1024 : 512;
    const int qtok0 = is_ng ? (T_ + n*T_ + t0) : t0;
    const float* maskrow = is_ng ? (mask_ng + (size_t)n * T_ * 1024) : mask_main;
    const int*   brow    = is_ng ? (ib_ng + (size_t)b * T_ * 1024)
                                 : (ib_main + (size_t)b * T_ * 512);

    const int tid = threadIdx.x;
    const int tx  = tid & 15, ty = tid >> 4;

    // Q^T tile
    #pragma unroll
    for (int p = 0; p < 4; p++) {
        int idx = tid + p*256;
        int r  = idx >> 4;
        int c4 = (idx & 15) << 2;
        float4 v = *(const float4*)(qkv + (size_t)((qtok0 + r)*B_ + b)*3072 + h*D_ + c4);
        sQt[(c4+0)*DP + r] = v.x; sQt[(c4+1)*DP + r] = v.y;
        sQt[(c4+2)*DP + r] = v.z; sQt[(c4+3)*DP + r] = v.w;
    }
    // rel LUT: per row, 32 bucket values for this head
    #pragma unroll
    for (int p = 0; p < 8; p++) {
        int idx = tid + p*256;          // 0..2047
        int r = idx >> 5, bk = idx & 31;
        sRel[r*32 + bk] = rel[(size_t)((qtok0 + r)*B_ + b)*512 + bk*H_ + h];
    }
    if (tid < 64) { sM[tid] = -1e30f; sL[tid] = 0.f; }

    ull accO[4][2];
    #pragma unroll
    for (int i = 0; i < 4; i++) { accO[i][0] = 0ull; accO[i][1] = 0ull; }

    for (int s0 = 0; s0 < S; s0 += BN2) {
        __syncthreads();   // (A) prev PV done with sK/sP; first iter: Q/rel ready
        // K^T tile
        #pragma unroll
        for (int p = 0; p < 4; p++) {
            int idx = tid + p*256;
            int sr = idx >> 4;
            int c4 = (idx & 15) << 2;
            int sg = s0 + sr;
            int tok = (!is_ng || sg < T_) ? sg : (T_ + n*T_ + (sg - T_));
            float4 v = *(const float4*)(qkv + (size_t)(tok*B_ + b)*3072 + 1024 + h*D_ + c4);
            sK[(c4+0)*DP + sr] = v.x; sK[(c4+1)*DP + sr] = v.y;
            sK[(c4+2)*DP + sr] = v.z; sK[(c4+3)*DP + sr] = v.w;
        }
        __syncthreads();   // (B) K ready

        // scores: 4 rows (ty*4..) x 4 cols (tx*4..) with f32x2
        ull acc[4][2];
        #pragma unroll
        for (int i = 0; i < 4; i++) { acc[i][0] = 0ull; acc[i][1] = 0ull; }
        #pragma unroll 8
        for (int kk = 0; kk < D_; kk++) {
            float4 a = *(const float4*)&sQt[kk*DP + ty*4];
            ull b0 = *(const ull*)&sK[kk*DP + tx*4];
            ull b1 = *(const ull*)&sK[kk*DP + tx*4 + 2];
            ull d;
            d = dup2(a.x); fma2(acc[0][0], d, b0); fma2(acc[0][1], d, b1);
            d = dup2(a.y); fma2(acc[1][0], d, b0); fma2(acc[1][1], d, b1);
            d = dup2(a.z); fma2(acc[2][0], d, b0); fma2(acc[2][1], d, b1);
            d = dup2(a.w); fma2(acc[3][0], d, b0); fma2(acc[3][1], d, b1);
        }
        // + rel(bucket) + mask -> sP
        #pragma unroll
        for (int i = 0; i < 4; i++) {
            int r  = ty*4 + i;
            int tg = t0 + r;
            const size_t base = (size_t)tg * S + s0 + tx*4;
            int4   bk = *(const int4*)&brow[base];
            float4 mk = *(const float4*)&maskrow[base];
            float2 v0 = unpack2(acc[i][0]);
            float2 v1 = unpack2(acc[i][1]);
            float4 o;
            o.x = v0.x + sRel[r*32 + bk.x] + mk.x;
            o.y = v0.y + sRel[r*32 + bk.y] + mk.y;
            o.z = v1.x + sRel[r*32 + bk.z] + mk.z;
            o.w = v1.y + sRel[r*32 + bk.w] + mk.w;
            *(float4*)&sP[r*DP + tx*4] = o;
        }
        __syncthreads();   // (C) sP ready; K reads done -> sK reusable for V

        // V tile [s][d]
        #pragma unroll
        for (int p = 0; p < 4; p++) {
            int idx = tid + p*256;
            int sr = idx >> 4;
            int c4 = (idx & 15) << 2;
            int sg = s0 + sr;
            int tok = (!is_ng || sg < T_) ? sg : (T_ + n*T_ + (sg - T_));
            float4 v = *(const float4*)(qkv + (size_t)(tok*B_ + b)*3072 + 2048 + h*D_ + c4);
            *(float4*)&sK[sr*DP + c4] = v;
        }

        // online softmax: 4 threads per row, 16 contiguous cols each
        {
            int r = tid >> 2, g = tid & 3;
            float* row = &sP[r*DP + g*16];
            float4 x0 = *(const float4*)(row);
            float4 x1 = *(const float4*)(row + 4);
            float4 x2 = *(const float4*)(row + 8);
            float4 x3 = *(const float4*)(row + 12);
            float mx = fmaxf(fmaxf(fmaxf(x0.x,x0.y),fmaxf(x0.z,x0.w)),
                      fmaxf(fmaxf(fmaxf(x1.x,x1.y),fmaxf(x1.z,x1.w)),
                      fmaxf(fmaxf(fmaxf(x2.x,x2.y),fmaxf(x2.z,x2.w)),
                            fmaxf(fmaxf(x3.x,x3.y),fmaxf(x3.z,x3.w)))));
            mx = fmaxf(mx, __shfl_xor_sync(0xffffffffu, mx, 1));
            mx = fmaxf(mx, __shfl_xor_sync(0xffffffffu, mx, 2));
            float oldm = sM[r];
            float newm = fmaxf(oldm, mx);
            x0.x = __expf(x0.x - newm); x0.y = __expf(x0.y - newm);
            x0.z = __expf(x0.z - newm); x0.w = __expf(x0.w - newm);
            x1.x = __expf(x1.x - newm); x1.y = __expf(x1.y - newm);
            x1.z = __expf(x1.z - newm); x1.w = __expf(x1.w - newm);
            x2.x = __expf(x2.x - newm); x2.y = __expf(x2.y - newm);
            x2.z = __expf(x2.z - newm); x2.w = __expf(x2.w - newm);
            x3.x = __expf(x3.x - newm); x3.y = __expf(x3.y - newm);
            x3.z = __expf(x3.z - newm); x3.w = __expf(x3.w - newm);
            float sum = (x0.x+x0.y+x0.z+x0.w) + (x1.x+x1.y+x1.z+x1.w)
                      + (x2.x+x2.y+x2.z+x2.w) + (x3.x+x3.y+x3.z+x3.w);
            sum += __shfl_xor_sync(0xffffffffu, sum, 1);
            sum += __shfl_xor_sync(0xffffffffu, sum, 2);
            *(float4*)(row)      = x0;
            *(float4*)(row + 4)  = x1;
            *(float4*)(row + 8)  = x2;
            *(float4*)(row + 12) = x3;
            if (g == 0) {
                float scl = __expf(oldm - newm);
                sScale[r] = scl;
                sL[r] = sL[r]*scl + sum;
                sM[r] = newm;
            }
        }
        __syncthreads();   // (D) V + exp(P) + sScale ready

        // rescale + PV (4 rows x 4 d-cols, f32x2)
        #pragma unroll
        for (int i = 0; i < 4; i++) {
            ull f = dup2(sScale[ty*4 + i]);
            accO[i][0] = mul2(accO[i][0], f);
            accO[i][1] = mul2(accO[i][1], f);
        }
        #pragma unroll 8
        for (int s = 0; s < BN2; s++) {
            ull v0 = *(const ull*)&sK[s*DP + tx*4];
            ull v1 = *(const ull*)&sK[s*DP + tx*4 + 2];
            ull p;
            p = dup2(sP[(ty*4+0)*DP + s]); fma2(accO[0][0], p, v0); fma2(accO[0][1], p, v1);
            p = dup2(sP[(ty*4+1)*DP + s]); fma2(accO[1][0], p, v0); fma2(accO[1][1], p, v1);
            p = dup2(sP[(ty*4+2)*DP + s]); fma2(accO[2][0], p, v0); fma2(accO[2][1], p, v1);
            p = dup2(sP[(ty*4+3)*DP + s]); fma2(accO[3][0], p, v0); fma2(accO[3][1], p, v1);
        }
    }

    #pragma unroll
    for (int i = 0; i < 4; i++) {
        int r = ty*4 + i;
        float inv = 1.f / sL[r];
        float2 a = unpack2(accO[i][0]);
        float2 c = unpack2(accO[i][1]);
        float4 o = make_float4(a.x*inv, a.y*inv, c.x*inv, c.y*inv);
        *(float4*)(ctx + (size_t)((qtok0 + r)*B_ + b)*1024 + h*D_ + tx*4) = o;
    }
}

#define SMEM_ATTN ((3*64*DP + 64*32 + 3*64) * 4)

// ---------------------------------------------------------------------------
extern "C" void kernel_launch(void* const* d_in, const int* in_sizes, int n_in,
                              void* d_out, int out_size)
{
    const float* hs        = (const float*)d_in[0];   // (1536,4,1024)
    const float* w_in      = (const float*)d_in[1];   // (3072,1024)
    const float* b_in      = (const float*)d_in[2];   // (3072,)
    const float* rw        = (const float*)d_in[3];   // (512,1024)
    const float* rb        = (const float*)d_in[4];   // (512,)
    const float* ow        = (const float*)d_in[5];   // (1024,1024)
    const float* ob        = (const float*)d_in[6];   // (1024,)
    const float* mask_main = (const float*)d_in[7];   // (512,512)
    const float* mask_ng   = (const float*)d_in[8];   // (2,512,1024)
    const int*   ib_main   = (const int*)d_in[9];     // (4,512,512)
    const int*   ib_ng     = (const int*)d_in[10];    // (4,512,1024)
    float* out = (float*)d_out;

    float *qkv, *rel, *ctx;
    cudaGetSymbolAddress((void**)&qkv, g_qkv);
    cudaGetSymbolAddress((void**)&rel, g_rel);
    cudaGetSymbolAddress((void**)&ctx, g_ctx);

    cudaFuncSetAttribute(attn_kernel, cudaFuncAttributeMaxDynamicSharedMemorySize, SMEM_ATTN);

    // QKV projection; q columns [0,1024) pre-scaled by d^-0.5 = 0.125
    sgemm_nt<<<dim3(3072/128, ROWS_/128), 256>>>(hs, w_in, b_in, qkv,
                                                 ROWS_, 3072, 1024, 1024, 0.125f);
    // rel-value table
    sgemm_nt<<<dim3(512/128, ROWS_/128), 256>>>(hs, rw, rb, rel,
                                                ROWS_, 512, 1024, 0, 1.f);
    // fused attention: z=0 main, z=1,2 ngram
    attn_kernel<<<dim3(T_/BM2, B_*H_, 3), 256, SMEM_ATTN>>>(
        qkv, rel, mask_main, mask_ng, ib_main, ib_ng, ctx);
    // out projection directly into d_out
    sgemm_nt<<<dim3(1024/128, ROWS_/128), 256>>>(ctx, ow, ob, out,
                                                 ROWS_, 1024, 1024, 0, 1.f);
}

// round 4
// speedup vs baseline: 1.3547x; 1.0682x over previous
#include <cuda_runtime.h>

#define T_ 512
#define B_ 4
#define H_ 16
#define D_ 64
#define NBKT 32
#define TOKENS 1536           // (1+NGRAM)*T
#define ROWS_ (TOKENS * B_)   // 6144

typedef unsigned long long ull;

// Scratch (device globals: allocation-free rule)
__device__ float g_qkv[ROWS_ * 3072];  // q|k|v per row, q pre-scaled by 1/8
__device__ float g_rel[ROWS_ * 512];   // rel-value table, col = bucket*16 + head
__device__ float g_ctx[ROWS_ * 1024];  // attention output pre out-proj

// ---- packed f32x2 helpers (SASS FFMA2 path; ptxas won't auto-fuse) ----
__device__ __forceinline__ ull dup2(float x) {
    ull r; asm("mov.b64 %0, {%1, %2};" : "=l"(r) : "f"(x), "f"(x)); return r;
}
__device__ __forceinline__ float2 unpack2(ull v) {
    float2 f; asm("mov.b64 {%0, %1}, %2;" : "=f"(f.x), "=f"(f.y) : "l"(v)); return f;
}
__device__ __forceinline__ void fma2(ull& d, ull a, ull b) {
    asm("fma.rn.f32x2 %0, %1, %2, %0;" : "+l"(d) : "l"(a), "l"(b));
}
__device__ __forceinline__ ull mul2(ull a, ull b) {
    ull r; asm("mul.rn.f32x2 %0, %1, %2;" : "=l"(r) : "l"(a), "l"(b)); return r;
}

// ---------------------------------------------------------------------------
// SGEMM v2: C[M,N] = A[M,K] @ B[N,K]^T + bias, cols < scale_cols scaled.
// Block 256x128, BK=16, double-buffered smem (1 barrier/iter), 256 threads.
// Per-thread 16x8 microtile as 8 row-pairs (f32x2), A needs no dup2.
// Requires: M % 256 == 0, N % 128 == 0, K % 16 == 0.
// ---------------------------------------------------------------------------
__global__ __launch_bounds__(256, 1) void sgemm_nt2(
    const float* __restrict__ A, const float* __restrict__ Bm,
    const float* __restrict__ bias, float* __restrict__ C,
    int M, int N, int K, int scale_cols, float scale)
{
    __shared__ float As[2][16][256];   // [buf][k][row]
    __shared__ float Bs[2][16][128];   // [buf][k][col]

    const int tid  = threadIdx.x;
    const int row0 = blockIdx.y * 256;
    const int col0 = blockIdx.x * 128;
    const int ty   = tid >> 4;         // 0..15 : row group of 16
    const int tx   = tid & 15;         // 0..15 : col group of 8
    const int brow = tid >> 1;         // 0..127
    const int blk  = (tid & 1) << 2;   // 0 or 4

    const float* Ap = A  + (size_t)(row0 + tid)  * K;
    const float* Bp = Bm + (size_t)(col0 + brow) * K + blk;

    ull acc[8][8];
    #pragma unroll
    for (int p = 0; p < 8; p++)
        #pragma unroll
        for (int j = 0; j < 8; j++) acc[p][j] = 0ull;

    // initial global->smem fill (buffer 0)
    {
        float4 a0 = *(const float4*)(Ap + 0);
        float4 a1 = *(const float4*)(Ap + 4);
        float4 a2 = *(const float4*)(Ap + 8);
        float4 a3 = *(const float4*)(Ap + 12);
        float4 b0 = *(const float4*)(Bp + 0);
        float4 b1 = *(const float4*)(Bp + 8);
        As[0][0][tid]=a0.x;  As[0][1][tid]=a0.y;  As[0][2][tid]=a0.z;  As[0][3][tid]=a0.w;
        As[0][4][tid]=a1.x;  As[0][5][tid]=a1.y;  As[0][6][tid]=a1.z;  As[0][7][tid]=a1.w;
        As[0][8][tid]=a2.x;  As[0][9][tid]=a2.y;  As[0][10][tid]=a2.z; As[0][11][tid]=a2.w;
        As[0][12][tid]=a3.x; As[0][13][tid]=a3.y; As[0][14][tid]=a3.z; As[0][15][tid]=a3.w;
        Bs[0][blk+0][brow]=b0.x; Bs[0][blk+1][brow]=b0.y;
        Bs[0][blk+2][brow]=b0.z; Bs[0][blk+3][brow]=b0.w;
        Bs[0][blk+8][brow]=b1.x; Bs[0][blk+9][brow]=b1.y;
        Bs[0][blk+10][brow]=b1.z; Bs[0][blk+11][brow]=b1.w;
    }
    __syncthreads();

    int cur = 0;
    for (int k0 = 0; k0 < K; k0 += 16) {
        const bool has = (k0 + 16) < K;
        float4 na0, na1, na2, na3, nb0, nb1;
        if (has) {
            na0 = *(const float4*)(Ap + k0 + 16);
            na1 = *(const float4*)(Ap + k0 + 20);
            na2 = *(const float4*)(Ap + k0 + 24);
            na3 = *(const float4*)(Ap + k0 + 28);
            nb0 = *(const float4*)(Bp + k0 + 16);
            nb1 = *(const float4*)(Bp + k0 + 24);
        }

        #pragma unroll
        for (int kk = 0; kk < 16; kk++) {
            const float* arow = &As[cur][kk][ty * 16];
            ulonglong2 A01 = *(const ulonglong2*)(arow);
            ulonglong2 A23 = *(const ulonglong2*)(arow + 4);
            ulonglong2 A45 = *(const ulonglong2*)(arow + 8);
            ulonglong2 A67 = *(const ulonglong2*)(arow + 12);
            float4 b0 = *(const float4*)&Bs[cur][kk][tx * 8];
            float4 b1 = *(const float4*)&Bs[cur][kk][tx * 8 + 4];
            ull bd0 = dup2(b0.x), bd1 = dup2(b0.y), bd2 = dup2(b0.z), bd3 = dup2(b0.w);
            ull bd4 = dup2(b1.x), bd5 = dup2(b1.y), bd6 = dup2(b1.z), bd7 = dup2(b1.w);
            ull ap[8] = {A01.x, A01.y, A23.x, A23.y, A45.x, A45.y, A67.x, A67.y};
            #pragma unroll
            for (int p = 0; p < 8; p++) {
                fma2(acc[p][0], ap[p], bd0);
                fma2(acc[p][1], ap[p], bd1);
                fma2(acc[p][2], ap[p], bd2);
                fma2(acc[p][3], ap[p], bd3);
                fma2(acc[p][4], ap[p], bd4);
                fma2(acc[p][5], ap[p], bd5);
                fma2(acc[p][6], ap[p], bd6);
                fma2(acc[p][7], ap[p], bd7);
            }
        }

        if (has) {
            int nxt = cur ^ 1;
            As[nxt][0][tid]=na0.x;  As[nxt][1][tid]=na0.y;  As[nxt][2][tid]=na0.z;  As[nxt][3][tid]=na0.w;
            As[nxt][4][tid]=na1.x;  As[nxt][5][tid]=na1.y;  As[nxt][6][tid]=na1.z;  As[nxt][7][tid]=na1.w;
            As[nxt][8][tid]=na2.x;  As[nxt][9][tid]=na2.y;  As[nxt][10][tid]=na2.z; As[nxt][11][tid]=na2.w;
            As[nxt][12][tid]=na3.x; As[nxt][13][tid]=na3.y; As[nxt][14][tid]=na3.z; As[nxt][15][tid]=na3.w;
            Bs[nxt][blk+0][brow]=nb0.x; Bs[nxt][blk+1][brow]=nb0.y;
            Bs[nxt][blk+2][brow]=nb0.z; Bs[nxt][blk+3][brow]=nb0.w;
            Bs[nxt][blk+8][brow]=nb1.x; Bs[nxt][blk+9][brow]=nb1.y;
            Bs[nxt][blk+10][brow]=nb1.z; Bs[nxt][blk+11][brow]=nb1.w;
            __syncthreads();
            cur = nxt;
        }
    }

    float4 bia0 = make_float4(0.f,0.f,0.f,0.f), bia1 = bia0;
    if (bias) {
        bia0 = *(const float4*)&bias[col0 + tx*8];
        bia1 = *(const float4*)&bias[col0 + tx*8 + 4];
    }
    const float bb[8] = {bia0.x,bia0.y,bia0.z,bia0.w,bia1.x,bia1.y,bia1.z,bia1.w};

    #pragma unroll
    for (int p = 0; p < 8; p++) {
        int r0 = row0 + ty*16 + 2*p;
        float o0[8], o1[8];
        #pragma unroll
        for (int j = 0; j < 8; j++) {
            float2 v = unpack2(acc[p][j]);
            o0[j] = v.x + bb[j];
            o1[j] = v.y + bb[j];
        }
        #pragma unroll
        for (int j = 0; j < 8; j++) {
            int c = col0 + tx*8 + j;
            if (c < scale_cols) { o0[j] *= scale; o1[j] *= scale; }
        }
        float* c0 = &C[(size_t)r0 * N + col0 + tx*8];
        float* c1 = c0 + N;
        *(float4*)(c0)     = make_float4(o0[0],o0[1],o0[2],o0[3]);
        *(float4*)(c0 + 4) = make_float4(o0[4],o0[5],o0[6],o0[7]);
        *(float4*)(c1)     = make_float4(o1[0],o1[1],o1[2],o1[3]);
        *(float4*)(c1 + 4) = make_float4(o1[4],o1[5],o1[6],o1[7]);
    }
}

// ---------------------------------------------------------------------------
// Fused flash attention (main + ngram in one launch), BM=64 x BN=64, d=64.
// 256 threads, 4x4 microtiles with f32x2 accumulators.
// grid: (T/64, B*H, 3) — z=0: main (S=512), z=1,2: ngram n=z-1 (S=1024).
// ---------------------------------------------------------------------------
#define BM2 64
#define BN2 64
#define DP  68

__global__ __launch_bounds__(256) void attn_kernel(
    const float* __restrict__ qkv, const float* __restrict__ rel,
    const float* __restrict__ mask_main, const float* __restrict__ mask_ng,
    const int* __restrict__ ib_main, const int* __restrict__ ib_ng,
    float* __restrict__ ctx)
{
    extern __shared__ float smem[];
    float* sQt   = smem;               // [64][DP]  Q^T (k-major)
    float* sK    = sQt + 64*DP;        // [64][DP]  K^T, later V[s][d]
    float* sP    = sK  + 64*DP;        // [64][DP]
    float* sRel  = sP  + 64*DP;        // [64][32]
    float* sM    = sRel + 64*32;
    float* sL    = sM + 64;
    float* sScale= sL + 64;

    const int bh = blockIdx.y;
    const int b  = bh >> 4;
    const int h  = bh & 15;
    const int z  = blockIdx.z;
    const int is_ng = (z > 0);
    const int n  = z - 1;
    const int t0 = blockIdx.x * BM2;
    const int S  = is_ng ? 1024 : 512;
    const int qtok0 = is_ng ? (T_ + n*T_ + t0) : t0;
    const float* maskrow = is_ng ? (mask_ng + (size_t)n * T_ * 1024) : mask_main;
    const int*   brow    = is_ng ? (ib_ng + (size_t)b * T_ * 1024)
                                 : (ib_main + (size_t)b * T_ * 512);

    const int tid = threadIdx.x;
    const int tx  = tid & 15, ty = tid >> 4;

    // Q^T tile
    #pragma unroll
    for (int p = 0; p < 4; p++) {
        int idx = tid + p*256;
        int r  = idx >> 4;
        int c4 = (idx & 15) << 2;
        float4 v = *(const float4*)(qkv + (size_t)((qtok0 + r)*B_ + b)*3072 + h*D_ + c4);
        sQt[(c4+0)*DP + r] = v.x; sQt[(c4+1)*DP + r] = v.y;
        sQt[(c4+2)*DP + r] = v.z; sQt[(c4+3)*DP + r] = v.w;
    }
    // rel LUT: per row, 32 bucket values for this head
    #pragma unroll
    for (int p = 0; p < 8; p++) {
        int idx = tid + p*256;          // 0..2047
        int r = idx >> 5, bk = idx & 31;
        sRel[r*32 + bk] = rel[(size_t)((qtok0 + r)*B_ + b)*512 + bk*H_ + h];
    }
    if (tid < 64) { sM[tid] = -1e30f; sL[tid] = 0.f; }

    ull accO[4][2];
    #pragma unroll
    for (int i = 0; i < 4; i++) { accO[i][0] = 0ull; accO[i][1] = 0ull; }

    for (int s0 = 0; s0 < S; s0 += BN2) {
        __syncthreads();   // (A) prev PV done with sK/sP; first iter: Q/rel ready
        // K^T tile
        #pragma unroll
        for (int p = 0; p < 4; p++) {
            int idx = tid + p*256;
            int sr = idx >> 4;
            int c4 = (idx & 15) << 2;
            int sg = s0 + sr;
            int tok = (!is_ng || sg < T_) ? sg : (T_ + n*T_ + (sg - T_));
            float4 v = *(const float4*)(qkv + (size_t)(tok*B_ + b)*3072 + 1024 + h*D_ + c4);
            sK[(c4+0)*DP + sr] = v.x; sK[(c4+1)*DP + sr] = v.y;
            sK[(c4+2)*DP + sr] = v.z; sK[(c4+3)*DP + sr] = v.w;
        }
        __syncthreads();   // (B) K ready

        // scores: 4 rows (ty*4..) x 4 cols (tx*4..) with f32x2
        ull acc[4][2];
        #pragma unroll
        for (int i = 0; i < 4; i++) { acc[i][0] = 0ull; acc[i][1] = 0ull; }
        #pragma unroll 8
        for (int kk = 0; kk < D_; kk++) {
            float4 a = *(const float4*)&sQt[kk*DP + ty*4];
            ull b0 = *(const ull*)&sK[kk*DP + tx*4];
            ull b1 = *(const ull*)&sK[kk*DP + tx*4 + 2];
            ull d;
            d = dup2(a.x); fma2(acc[0][0], d, b0); fma2(acc[0][1], d, b1);
            d = dup2(a.y); fma2(acc[1][0], d, b0); fma2(acc[1][1], d, b1);
            d = dup2(a.z); fma2(acc[2][0], d, b0); fma2(acc[2][1], d, b1);
            d = dup2(a.w); fma2(acc[3][0], d, b0); fma2(acc[3][1], d, b1);
        }
        // + rel(bucket) + mask -> sP
        #pragma unroll
        for (int i = 0; i < 4; i++) {
            int r  = ty*4 + i;
            int tg = t0 + r;
            const size_t base = (size_t)tg * S + s0 + tx*4;
            int4   bk = *(const int4*)&brow[base];
            float4 mk = *(const float4*)&maskrow[base];
            float2 v0 = unpack2(acc[i][0]);
            float2 v1 = unpack2(acc[i][1]);
            float4 o;
            o.x = v0.x + sRel[r*32 + bk.x] + mk.x;
            o.y = v0.y + sRel[r*32 + bk.y] + mk.y;
            o.z = v1.x + sRel[r*32 + bk.z] + mk.z;
            o.w = v1.y + sRel[r*32 + bk.w] + mk.w;
            *(float4*)&sP[r*DP + tx*4] = o;
        }
        __syncthreads();   // (C) sP ready; K reads done -> sK reusable for V

        // V tile [s][d]
        #pragma unroll
        for (int p = 0; p < 4; p++) {
            int idx = tid + p*256;
            int sr = idx >> 4;
            int c4 = (idx & 15) << 2;
            int sg = s0 + sr;
            int tok = (!is_ng || sg < T_) ? sg : (T_ + n*T_ + (sg - T_));
            float4 v = *(const float4*)(qkv + (size_t)(tok*B_ + b)*3072 + 2048 + h*D_ + c4);
            *(float4*)&sK[sr*DP + c4] = v;
        }

        // online softmax: 4 threads per row, 16 contiguous cols each
        {
            int r = tid >> 2, g = tid & 3;
            float* row = &sP[r*DP + g*16];
            float4 x0 = *(const float4*)(row);
            float4 x1 = *(const float4*)(row + 4);
            float4 x2 = *(const float4*)(row + 8);
            float4 x3 = *(const float4*)(row + 12);
            float mx = fmaxf(fmaxf(fmaxf(x0.x,x0.y),fmaxf(x0.z,x0.w)),
                      fmaxf(fmaxf(fmaxf(x1.x,x1.y),fmaxf(x1.z,x1.w)),
                      fmaxf(fmaxf(fmaxf(x2.x,x2.y),fmaxf(x2.z,x2.w)),
                            fmaxf(fmaxf(x3.x,x3.y),fmaxf(x3.z,x3.w)))));
            mx = fmaxf(mx, __shfl_xor_sync(0xffffffffu, mx, 1));
            mx = fmaxf(mx, __shfl_xor_sync(0xffffffffu, mx, 2));
            float oldm = sM[r];
            float newm = fmaxf(oldm, mx);
            x0.x = __expf(x0.x - newm); x0.y = __expf(x0.y - newm);
            x0.z = __expf(x0.z - newm); x0.w = __expf(x0.w - newm);
            x1.x = __expf(x1.x - newm); x1.y = __expf(x1.y - newm);
            x1.z = __expf(x1.z - newm); x1.w = __expf(x1.w - newm);
            x2.x = __expf(x2.x - newm); x2.y = __expf(x2.y - newm);
            x2.z = __expf(x2.z - newm); x2.w = __expf(x2.w - newm);
            x3.x = __expf(x3.x - newm); x3.y = __expf(x3.y - newm);
            x3.z = __expf(x3.z - newm); x3.w = __expf(x3.w - newm);
            float sum = (x0.x+x0.y+x0.z+x0.w) + (x1.x+x1.y+x1.z+x1.w)
                      + (x2.x+x2.y+x2.z+x2.w) + (x3.x+x3.y+x3.z+x3.w);
            sum += __shfl_xor_sync(0xffffffffu, sum, 1);
            sum += __shfl_xor_sync(0xffffffffu, sum, 2);
            *(float4*)(row)      = x0;
            *(float4*)(row + 4)  = x1;
            *(float4*)(row + 8)  = x2;
            *(float4*)(row + 12) = x3;
            if (g == 0) {
                float scl = __expf(oldm - newm);
                sScale[r] = scl;
                sL[r] = sL[r]*scl + sum;
                sM[r] = newm;
            }
        }
        __syncthreads();   // (D) V + exp(P) + sScale ready

        // rescale + PV (4 rows x 4 d-cols, f32x2)
        #pragma unroll
        for (int i = 0; i < 4; i++) {
            ull f = dup2(sScale[ty*4 + i]);
            accO[i][0] = mul2(accO[i][0], f);
            accO[i][1] = mul2(accO[i][1], f);
        }
        #pragma unroll 8
        for (int s = 0; s < BN2; s++) {
            ull v0 = *(const ull*)&sK[s*DP + tx*4];
            ull v1 = *(const ull*)&sK[s*DP + tx*4 + 2];
            ull p;
            p = dup2(sP[(ty*4+0)*DP + s]); fma2(accO[0][0], p, v0); fma2(accO[0][1], p, v1);
            p = dup2(sP[(ty*4+1)*DP + s]); fma2(accO[1][0], p, v0); fma2(accO[1][1], p, v1);
            p = dup2(sP[(ty*4+2)*DP + s]); fma2(accO[2][0], p, v0); fma2(accO[2][1], p, v1);
            p = dup2(sP[(ty*4+3)*DP + s]); fma2(accO[3][0], p, v0); fma2(accO[3][1], p, v1);
        }
    }

    #pragma unroll
    for (int i = 0; i < 4; i++) {
        int r = ty*4 + i;
        float inv = 1.f / sL[r];
        float2 a = unpack2(accO[i][0]);
        float2 c = unpack2(accO[i][1]);
        float4 o = make_float4(a.x*inv, a.y*inv, c.x*inv, c.y*inv);
        *(float4*)(ctx + (size_t)((qtok0 + r)*B_ + b)*1024 + h*D_ + tx*4) = o;
    }
}

#define SMEM_ATTN ((3*64*DP + 64*32 + 3*64) * 4)

// ---------------------------------------------------------------------------
extern "C" void kernel_launch(void* const* d_in, const int* in_sizes, int n_in,
                              void* d_out, int out_size)
{
    const float* hs        = (const float*)d_in[0];   // (1536,4,1024)
    const float* w_in      = (const float*)d_in[1];   // (3072,1024)
    const float* b_in      = (const float*)d_in[2];   // (3072,)
    const float* rw        = (const float*)d_in[3];   // (512,1024)
    const float* rb        = (const float*)d_in[4];   // (512,)
    const float* ow        = (const float*)d_in[5];   // (1024,1024)
    const float* ob        = (const float*)d_in[6];   // (1024,)
    const float* mask_main = (const float*)d_in[7];   // (512,512)
    const float* mask_ng   = (const float*)d_in[8];   // (2,512,1024)
    const int*   ib_main   = (const int*)d_in[9];     // (4,512,512)
    const int*   ib_ng     = (const int*)d_in[10];    // (4,512,1024)
    float* out = (float*)d_out;

    float *qkv, *rel, *ctx;
    cudaGetSymbolAddress((void**)&qkv, g_qkv);
    cudaGetSymbolAddress((void**)&rel, g_rel);
    cudaGetSymbolAddress((void**)&ctx, g_ctx);

    cudaFuncSetAttribute(attn_kernel, cudaFuncAttributeMaxDynamicSharedMemorySize, SMEM_ATTN);

    // QKV projection; q columns [0,1024) pre-scaled by d^-0.5 = 0.125
    sgemm_nt2<<<dim3(3072/128, ROWS_/256), 256>>>(hs, w_in, b_in, qkv,
                                                  ROWS_, 3072, 1024, 1024, 0.125f);
    // rel-value table
    sgemm_nt2<<<dim3(512/128, ROWS_/256), 256>>>(hs, rw, rb, rel,
                                                 ROWS_, 512, 1024, 0, 1.f);
    // fused attention: z=0 main, z=1,2 ngram
    attn_kernel<<<dim3(T_/BM2, B_*H_, 3), 256, SMEM_ATTN>>>(
        qkv, rel, mask_main, mask_ng, ib_main, ib_ng, ctx);
    // out projection directly into d_out
    sgemm_nt2<<<dim3(1024/128, ROWS_/256), 256>>>(ctx, ow, ob, out,
                                                  ROWS_, 1024, 1024, 0, 1.f);
}